// round 14
// baseline (speedup 1.0000x reference)
#include <cuda_runtime.h>
#include <math.h>

#define BB 2
#define SS 512
#define HH 128
#define AA 7
#define T1 8
#define EPSF 1e-5f
#define NTILES 2048   // 16i x 32j tiles
#define K2_GRID 888   // 6 blocks/SM * 148
#define NROWU (2 * BB * SS / 8 + BB)   // 256 pointer row-groups + 2 action units

typedef unsigned long long ull;

// Scratch
__device__ float g_proj[4][BB * SS * HH];
__device__ float g_logits[BB * SS * AA];
__device__ float g_wg[2][HH];
__device__ float g_c[2][2];
__device__ unsigned int g_tile_ctr;
__device__ unsigned int g_tile_done;
__device__ unsigned int g_row_ctr;

// ---------------- packed f32x2 helpers (sm_103a) ----------------
__device__ __forceinline__ ull pk(float lo, float hi) {
    ull r; asm("mov.b64 %0, {%1, %2};" : "=l"(r) : "f"(lo), "f"(hi)); return r;
}
__device__ __forceinline__ void upk(ull v, float& lo, float& hi) {
    asm("mov.b64 {%0, %1}, %2;" : "=f"(lo), "=f"(hi) : "l"(v));
}
__device__ __forceinline__ ull add2(ull a, ull b) {
    ull r; asm("add.rn.f32x2 %0, %1, %2;" : "=l"(r) : "l"(a), "l"(b)); return r;
}
__device__ __forceinline__ ull mul2(ull a, ull b) {
    ull r; asm("mul.rn.f32x2 %0, %1, %2;" : "=l"(r) : "l"(a), "l"(b)); return r;
}
__device__ __forceinline__ ull fma2(ull a, ull b, ull c) {
    ull r; asm("fma.rn.f32x2 %0, %1, %2, %3;" : "=l"(r) : "l"(a), "l"(b), "l"(c)); return r;
}
// tanh on both halves of a packed f32x2
__device__ __forceinline__ ull tanh2(ull u) {
    ull r;
    asm("{\n\t.reg .f32 lo, hi;\n\t"
        "mov.b64 {lo, hi}, %1;\n\t"
        "tanh.approx.f32 lo, lo;\n\t"
        "tanh.approx.f32 hi, hi;\n\t"
        "mov.b64 %0, {lo, hi};\n\t}"
        : "=l"(r) : "l"(u));
    return r;
}

__device__ __forceinline__ float tanh_fast(float x) {
    float y; asm("tanh.approx.f32 %0, %1;" : "=f"(y) : "f"(x)); return y;
}
__device__ __forceinline__ float gelu_t(float x) {
    float x2 = x * x;
    float u = x * fmaf(0.7978845608f * 0.044715f, x2, 0.7978845608f);
    float t = tanh_fast(u);
    float xh = 0.5f * x;
    return fmaf(xh, t, xh);
}

// ---------------- reductions ----------------
__device__ __forceinline__ float warpSum(float v) {
#pragma unroll
    for (int o = 16; o; o >>= 1) v += __shfl_xor_sync(0xffffffffu, v, o);
    return v;
}
__device__ __forceinline__ float warpMax(float v) {
#pragma unroll
    for (int o = 16; o; o >>= 1) v = fmaxf(v, __shfl_xor_sync(0xffffffffu, v, o));
    return v;
}
// block sum for blockDim.x == 256
__device__ __forceinline__ float blockSum256(float v, float* red8) {
    v = warpSum(v);
    __syncthreads();
    if ((threadIdx.x & 31) == 0) red8[threadIdx.x >> 5] = v;
    __syncthreads();
    return red8[0] + red8[1] + red8[2] + red8[3] + red8[4] + red8[5] + red8[6] + red8[7];
}

// kA: tiled projections + prep (block (0,0)) + action head tail (m==4).
// Best-measured configuration: grid = (128, 5), block = 256.
__global__ __launch_bounds__(256) void kA_proj(
        const float* __restrict__ hid,
        const float* __restrict__ w0, const float* __restrict__ b0,
        const float* __restrict__ w1, const float* __restrict__ b1,
        const float* __restrict__ w2, const float* __restrict__ b2,
        const float* __restrict__ w3, const float* __restrict__ b3,
        const float* __restrict__ w4, const float* __restrict__ b4,
        const float* __restrict__ lpw, const float* __restrict__ lg,
        const float* __restrict__ lb,  const float* __restrict__ lpb,
        const float* __restrict__ rpw, const float* __restrict__ rg,
        const float* __restrict__ rb,  const float* __restrict__ rpb,
        const float* __restrict__ alg, const float* __restrict__ alb,
        const float* __restrict__ aw2, const float* __restrict__ ab2) {
    __shared__ float sh[HH * 12];        // token tile [feature][token], stride 12
    __shared__ ull   comb[128 * 5];      // kh=1 partial accs (stride 5)
    __shared__ float red8[8];
    int m = blockIdx.y;
    int tid = threadIdx.x;
    int j = tid & 127, kh = tid >> 7;

    // --- prep (one block only): constants + counter resets for k2D ---
    if (m == 0 && blockIdx.x == 0) {
        if (tid == 0) { g_tile_ctr = 0u; g_tile_done = 0u; g_row_ctr = 0u; }
#pragma unroll
        for (int head = 0; head < 2; head++) {
            const float* pw = head ? rpw : lpw;
            const float* gg = head ? rg  : lg;
            const float* bv = head ? rb  : lb;
            const float* pb = head ? rpb : lpb;
            float v1 = 0.f, v2 = 0.f;
            if (tid < HH) {
                float w = pw[tid];
                float wg = w * gg[tid];
                g_wg[head][tid] = wg;
                v1 = wg;
                v2 = w * bv[tid];
            }
            float c1 = blockSum256(v1, red8);
            float c2 = blockSum256(v2, red8);
            if (tid == 0) { g_c[head][0] = c1; g_c[head][1] = c2 + pb[0]; }
            __syncthreads();
        }
    }

    const float* W; const float* B;
    if      (m == 0) { W = w0; B = b0; }
    else if (m == 1) { W = w1; B = b1; }
    else if (m == 2) { W = w2; B = b2; }
    else if (m == 3) { W = w3; B = b3; }
    else             { W = w4; B = b4; }

    int t0 = blockIdx.x * T1;
    for (int idx = tid; idx < T1 * HH; idx += 256) {
        int t = idx >> 7, c = idx & 127;
        sh[c * 12 + t] = hid[(t0 + t) * HH + c];
    }
    __syncthreads();

    // Each thread reduces K rows [kh*64, kh*64+64) with 8-deep prefetch.
    const float* Wh = W + (kh * 64) * HH + j;
    ull acc[4];
    if (kh == 0) {
        float bj = B[j];
        ull bj2 = pk(bj, bj);
#pragma unroll
        for (int q = 0; q < 4; q++) acc[q] = bj2;
    } else {
#pragma unroll
        for (int q = 0; q < 4; q++) acc[q] = 0ull;
    }

    float wcur[8];
#pragma unroll
    for (int u = 0; u < 8; u++) wcur[u] = Wh[u * HH];
#pragma unroll
    for (int kb = 0; kb < 64; kb += 8) {
        float wnxt[8];
        if (kb + 8 < 64) {
#pragma unroll
            for (int u = 0; u < 8; u++) wnxt[u] = Wh[(kb + 8 + u) * HH];
        }
#pragma unroll
        for (int u = 0; u < 8; u++) {
            ull wv = pk(wcur[u], wcur[u]);
            const float4* hp4 = (const float4*)&sh[(kh * 64 + kb + u) * 12];
            float4 f0 = hp4[0], f1 = hp4[1];
            acc[0] = fma2(pk(f0.x, f0.y), wv, acc[0]);
            acc[1] = fma2(pk(f0.z, f0.w), wv, acc[1]);
            acc[2] = fma2(pk(f1.x, f1.y), wv, acc[2]);
            acc[3] = fma2(pk(f1.z, f1.w), wv, acc[3]);
        }
        if (kb + 8 < 64) {
#pragma unroll
            for (int u = 0; u < 8; u++) wcur[u] = wnxt[u];
        }
    }

    // Combine the two K halves.
    if (kh) {
        ull* cc = &comb[j * 5];
#pragma unroll
        for (int q = 0; q < 4; q++) cc[q] = acc[q];
    }
    __syncthreads();
    if (!kh) {
        const ull* cc = &comb[j * 5];
#pragma unroll
        for (int q = 0; q < 4; q++) acc[q] = add2(acc[q], cc[q]);
    }

    if (m < 4) {
        if (!kh) {
            float* O = g_proj[m];
#pragma unroll
            for (int q = 0; q < 4; q++) {
                float lo, hi; upk(acc[q], lo, hi);
                O[(t0 + 2 * q) * HH + j] = lo;
                O[(t0 + 2 * q + 1) * HH + j] = hi;
            }
        }
    } else {
        // action tail: gelu -> LN -> 7 logits, in-smem (sh reused, stride 129).
        __syncthreads();
        if (!kh) {
#pragma unroll
            for (int q = 0; q < 4; q++) {
                float lo, hi; upk(acc[q], lo, hi);
                sh[(2 * q) * 129 + j]     = gelu_t(lo);
                sh[(2 * q + 1) * 129 + j] = gelu_t(hi);
            }
        }
        __syncthreads();
        if (tid < 128) {
            int w = tid >> 5, l = tid & 31;
#pragma unroll
            for (int tt = 0; tt < 2; tt++) {
                int t = w * 2 + tt;
                float v[4];
                float s = 0.f, s2 = 0.f;
#pragma unroll
                for (int k = 0; k < 4; k++) {
                    v[k] = sh[t * 129 + l + 32 * k];
                    s += v[k];
                    s2 = fmaf(v[k], v[k], s2);
                }
                s = warpSum(s);
                s2 = warpSum(s2);
                float mean = s * (1.0f / HH);
                float var = s2 * (1.0f / HH) - mean * mean;
                float rstd = rsqrtf(var + EPSF);
                float ln[4];
#pragma unroll
                for (int k = 0; k < 4; k++) {
                    int jj = l + 32 * k;
                    ln[k] = fmaf((v[k] - mean) * rstd, alg[jj], alb[jj]);
                }
#pragma unroll
                for (int a = 0; a < AA; a++) {
                    float d = 0.f;
#pragma unroll
                    for (int k = 0; k < 4; k++) {
                        int jj = l + 32 * k;
                        d = fmaf(ln[k], aw2[jj * AA + a], d);
                    }
                    d = warpSum(d);
                    if (l == 0) g_logits[(t0 + t) * AA + a] = d + ab2[a];
                }
            }
        }
    }
}

// k2D: fused pointer scores + log-softmaxes. Persistent grid.
// Phase T: tiles (16i x 32j) from g_tile_ctr; each completed tile bumps
//          g_tile_done (store -> fence -> bar -> inc).
// Phase S: after g_tile_done == NTILES, row units from g_row_ctr:
//          units [0,256): 8 pointer rows each; units 256,257: action lsm (b).
__global__ __launch_bounds__(256, 6) void k2_scores(float* __restrict__ out) {
    __shared__ float hd_s[16 * HH];     // [i][h]
    __shared__ float2 hv_s[65 * 33];    // [hh][j], padding row for prefetch
    __shared__ float wg_s[2][HH + 2];   // padded
    __shared__ unsigned int s_claim;

    int tid = threadIdx.x;
    if (tid < HH) { wg_s[0][tid] = g_wg[0][tid]; wg_s[1][tid] = g_wg[1][tid]; }
    if (tid < 2)  { wg_s[tid][HH] = 0.f; wg_s[tid][HH + 1] = 0.f; }

    const ull cA = pk(0.7978845608f * 0.044715f, 0.7978845608f * 0.044715f);
    const ull cB = pk(0.7978845608f, 0.7978845608f);

    int jl = tid & 31;
    int ib = (tid >> 5) * 2;   // warp's 2 i-rows

    // ---------------- Phase T: score tiles ----------------
    while (true) {
        if (tid == 0) s_claim = atomicAdd(&g_tile_ctr, 1u);
        __syncthreads();               // orders s_claim AND protects smem reuse
        unsigned int tile = s_claim;
        if (tile >= NTILES) break;

        int bh = tile >> 9;                       // 4 (b,head) groups
        int b = bh >> 1, head = bh & 1;
        int rest = tile & 511;
        int i0 = (rest >> 4) * 16, j0 = (rest & 15) * 32;

        const float* hv = g_proj[head * 2 + 0] + b * SS * HH;
        const float* hd = g_proj[head * 2 + 1] + b * SS * HH;

        {
            const float4* src = (const float4*)(hd + i0 * HH);
            float4* dst = (float4*)hd_s;
            for (int k = tid; k < 16 * HH / 4; k += 256) dst[k] = src[k];
        }
        {
            int j = tid >> 3;
            int cg = tid & 7;
            const float4* src = (const float4*)(hv + (j0 + j) * HH + cg * 16);
#pragma unroll
            for (int q = 0; q < 4; q++) {
                float4 v = src[q];
                int hh = cg * 8 + q * 2;
                hv_s[hh * 33 + j] = make_float2(v.x, v.y);
                hv_s[(hh + 1) * 33 + j] = make_float2(v.z, v.w);
            }
        }
        __syncthreads();

        const ull* hdb = (const ull*)&hd_s[ib * HH];   // rows ib, ib+1
        const ull* wgp = (const ull*)wg_s[head];
        const ull* hvp = (const ull*)hv_s + jl;

        // accumulate y = 2*gelu(x):  y = x + x*tanh(u)
        ull s0[2], s1[2], sd[2];
#pragma unroll
        for (int i = 0; i < 2; i++) { s0[i] = 0ull; s1[i] = 0ull; sd[i] = 0ull; }

        ull hvv = hvp[0];
        ull wgv = wgp[0];
#pragma unroll 4
        for (int hh = 0; hh < HH / 2; hh++) {
            ull hvv_n = hvp[(hh + 1) * 33];   // row 64 = padding row, safe
            ull wgv_n = wgp[hh + 1];          // element 64 = padding, safe
#pragma unroll
            for (int i = 0; i < 2; i++) {
                ull x  = add2(hdb[i * 64 + hh], hvv);
                ull x2 = mul2(x, x);
                ull u  = mul2(x, fma2(cA, x2, cB));
                ull t  = tanh2(u);
                ull y  = fma2(x, t, x);
                s0[i] = add2(s0[i], y);
                s1[i] = fma2(y, y, s1[i]);
                sd[i] = fma2(wgv, y, sd[i]);
            }
            hvv = hvv_n;
            wgv = wgv_n;
        }

        float c1 = g_c[head][0], c2 = g_c[head][1];
        float* op = out + BB * SS * AA + head * (BB * SS * SS) + b * (SS * SS)
                  + (i0 + ib) * SS + (j0 + jl);
#pragma unroll
        for (int i = 0; i < 2; i++) {
            float a0, a1, q0, q1, d0, d1;
            upk(s0[i], a0, a1); upk(s1[i], q0, q1); upk(sd[i], d0, d1);
            float fs0 = a0 + a1, fs1 = q0 + q1, fsd = d0 + d1;
            float m    = fs0 * (1.0f / (2.0f * HH));
            float eg2  = fs1 * (1.0f / (4.0f * HH));
            float var  = eg2 - m * m;
            float rstd = rsqrtf(var + EPSF);
            float score = fmaf(rstd, fmaf(-m, c1, 0.5f * fsd), c2);
            op[i * SS] = score;
        }

        // publish this tile's scores, then count it done
        __threadfence();
        __syncthreads();
        if (tid == 0) atomicAdd(&g_tile_done, 1u);
    }

    // ---------------- barrier: all tiles complete ----------------
    if (tid == 0) {
        while (atomicAdd(&g_tile_done, 0u) < NTILES) { }
    }
    __syncthreads();
    __threadfence();   // acquire-side ordering before reading scores

    // ---------------- Phase S: log-softmaxes ----------------
    int w = tid >> 5, l = tid & 31;
    while (true) {
        if (tid == 0) s_claim = atomicAdd(&g_row_ctr, 1u);
        __syncthreads();
        unsigned int ru = s_claim;
        if (ru >= NROWU) break;

        if (ru < (unsigned)(2 * BB * SS / 8)) {
            int row = ru * 8 + w;
            float4* p = (float4*)(out + BB * SS * AA + row * SS);
            float4 v[4];
            float mx = -INFINITY;
#pragma unroll
            for (int k = 0; k < 4; k++) {
                v[k] = p[l + 32 * k];
                mx = fmaxf(mx, fmaxf(fmaxf(v[k].x, v[k].y), fmaxf(v[k].z, v[k].w)));
            }
            mx = warpMax(mx);
            float s = 0.f;
#pragma unroll
            for (int k = 0; k < 4; k++)
                s += __expf(v[k].x - mx) + __expf(v[k].y - mx) + __expf(v[k].z - mx) + __expf(v[k].w - mx);
            s = warpSum(s);
            float lgs = mx + __logf(s);
#pragma unroll
            for (int k = 0; k < 4; k++) {
                v[k].x -= lgs; v[k].y -= lgs; v[k].z -= lgs; v[k].w -= lgs;
                p[l + 32 * k] = v[k];
            }
        } else {
            int b = ru - 2 * BB * SS / 8;
            if (w < AA) {
                int a = w;
                const float* lg2 = g_logits + b * SS * AA + a;
                float v[16];
                float mx = -INFINITY;
#pragma unroll
                for (int k = 0; k < 16; k++) {
                    v[k] = lg2[(l + 32 * k) * AA];
                    mx = fmaxf(mx, v[k]);
                }
                mx = warpMax(mx);
                float s = 0.f;
#pragma unroll
                for (int k = 0; k < 16; k++) s += __expf(v[k] - mx);
                s = warpSum(s);
                float lgs = mx + __logf(s);
                float* o = out + b * SS * AA + a;
#pragma unroll
                for (int k = 0; k < 16; k++) o[(l + 32 * k) * AA] = v[k] - lgs;
            }
        }
        __syncthreads();   // protect s_claim reuse
    }
}

extern "C" void kernel_launch(void* const* d_in, const int* in_sizes, int n_in,
                              void* d_out, int out_size) {
    const float* hiddens = (const float*)d_in[0];
    const float* aw1     = (const float*)d_in[1];
    const float* ab1     = (const float*)d_in[2];
    const float* a_ln_g  = (const float*)d_in[3];
    const float* a_ln_b  = (const float*)d_in[4];
    const float* aw2     = (const float*)d_in[5];
    const float* ab2     = (const float*)d_in[6];
    const float* lhid_w  = (const float*)d_in[7];
    const float* lhid_b  = (const float*)d_in[8];
    const float* lhead_w = (const float*)d_in[9];
    const float* lhead_b = (const float*)d_in[10];
    const float* l_ln_g  = (const float*)d_in[11];
    const float* l_ln_b  = (const float*)d_in[12];
    const float* l_proj_w = (const float*)d_in[13];
    const float* l_proj_b = (const float*)d_in[14];
    const float* rhid_w  = (const float*)d_in[15];
    const float* rhid_b  = (const float*)d_in[16];
    const float* rhead_w = (const float*)d_in[17];
    const float* rhead_b = (const float*)d_in[18];
    const float* r_ln_g  = (const float*)d_in[19];
    const float* r_ln_b  = (const float*)d_in[20];
    const float* r_proj_w = (const float*)d_in[21];
    const float* r_proj_b = (const float*)d_in[22];
    float* out = (float*)d_out;

    kA_proj<<<dim3(BB * SS / T1, 5), 256>>>(hiddens,
        lhid_w, lhid_b, lhead_w, lhead_b, rhid_w, rhid_b, rhead_w, rhead_b, aw1, ab1,
        l_proj_w, l_ln_g, l_ln_b, l_proj_b, r_proj_w, r_ln_g, r_ln_b, r_proj_b,
        a_ln_g, a_ln_b, aw2, ab2);
    k2_scores<<<K2_GRID, 256>>>(out);
}

// round 15
// speedup vs baseline: 1.0992x; 1.0992x over previous
#include <cuda_runtime.h>
#include <math.h>

#define BB 2
#define SS 512
#define HH 128
#define AA 7
#define T1 8
#define EPSF 1e-5f
#define NTILES 2048   // 16i x 32j tiles
#define K2_GRID 888   // 6 blocks/SM * 148

typedef unsigned long long ull;

// Scratch
__device__ float g_proj[4][BB * SS * HH];
__device__ float g_logits[BB * SS * AA];
__device__ float g_wg[2][HH];
__device__ float g_c[2][2];
__device__ unsigned int g_tile_ctr;

// ---------------- packed f32x2 helpers (sm_103a) ----------------
__device__ __forceinline__ ull pk(float lo, float hi) {
    ull r; asm("mov.b64 %0, {%1, %2};" : "=l"(r) : "f"(lo), "f"(hi)); return r;
}
__device__ __forceinline__ void upk(ull v, float& lo, float& hi) {
    asm("mov.b64 {%0, %1}, %2;" : "=f"(lo), "=f"(hi) : "l"(v));
}
__device__ __forceinline__ ull add2(ull a, ull b) {
    ull r; asm("add.rn.f32x2 %0, %1, %2;" : "=l"(r) : "l"(a), "l"(b)); return r;
}
__device__ __forceinline__ ull mul2(ull a, ull b) {
    ull r; asm("mul.rn.f32x2 %0, %1, %2;" : "=l"(r) : "l"(a), "l"(b)); return r;
}
__device__ __forceinline__ ull fma2(ull a, ull b, ull c) {
    ull r; asm("fma.rn.f32x2 %0, %1, %2, %3;" : "=l"(r) : "l"(a), "l"(b), "l"(c)); return r;
}
// tanh on both halves of a packed f32x2
__device__ __forceinline__ ull tanh2(ull u) {
    ull r;
    asm("{\n\t.reg .f32 lo, hi;\n\t"
        "mov.b64 {lo, hi}, %1;\n\t"
        "tanh.approx.f32 lo, lo;\n\t"
        "tanh.approx.f32 hi, hi;\n\t"
        "mov.b64 %0, {lo, hi};\n\t}"
        : "=l"(r) : "l"(u));
    return r;
}

__device__ __forceinline__ float tanh_fast(float x) {
    float y; asm("tanh.approx.f32 %0, %1;" : "=f"(y) : "f"(x)); return y;
}
__device__ __forceinline__ float gelu_t(float x) {
    float x2 = x * x;
    float u = x * fmaf(0.7978845608f * 0.044715f, x2, 0.7978845608f);
    float t = tanh_fast(u);
    float xh = 0.5f * x;
    return fmaf(xh, t, xh);
}

// ---------------- reductions ----------------
__device__ __forceinline__ float warpSum(float v) {
#pragma unroll
    for (int o = 16; o; o >>= 1) v += __shfl_xor_sync(0xffffffffu, v, o);
    return v;
}
__device__ __forceinline__ float warpMax(float v) {
#pragma unroll
    for (int o = 16; o; o >>= 1) v = fmaxf(v, __shfl_xor_sync(0xffffffffu, v, o));
    return v;
}
// block sum for blockDim.x == 256
__device__ __forceinline__ float blockSum256(float v, float* red8) {
    v = warpSum(v);
    __syncthreads();
    if ((threadIdx.x & 31) == 0) red8[threadIdx.x >> 5] = v;
    __syncthreads();
    return red8[0] + red8[1] + red8[2] + red8[3] + red8[4] + red8[5] + red8[6] + red8[7];
}

// kA: tiled projections + prep (block (0,0)) + action head tail (m==4).
// Best-measured configuration: grid = (128, 5), block = 256.
__global__ __launch_bounds__(256) void kA_proj(
        const float* __restrict__ hid,
        const float* __restrict__ w0, const float* __restrict__ b0,
        const float* __restrict__ w1, const float* __restrict__ b1,
        const float* __restrict__ w2, const float* __restrict__ b2,
        const float* __restrict__ w3, const float* __restrict__ b3,
        const float* __restrict__ w4, const float* __restrict__ b4,
        const float* __restrict__ lpw, const float* __restrict__ lg,
        const float* __restrict__ lb,  const float* __restrict__ lpb,
        const float* __restrict__ rpw, const float* __restrict__ rg,
        const float* __restrict__ rb,  const float* __restrict__ rpb,
        const float* __restrict__ alg, const float* __restrict__ alb,
        const float* __restrict__ aw2, const float* __restrict__ ab2) {
    __shared__ float sh[HH * 12];        // token tile [feature][token], stride 12
    __shared__ ull   comb[128 * 5];      // kh=1 partial accs (stride 5)
    __shared__ float red8[8];
    int m = blockIdx.y;
    int tid = threadIdx.x;
    int j = tid & 127, kh = tid >> 7;

    // --- prep (one block only) ---
    if (m == 0 && blockIdx.x == 0) {
        if (tid == 0) g_tile_ctr = 0u;
#pragma unroll
        for (int head = 0; head < 2; head++) {
            const float* pw = head ? rpw : lpw;
            const float* gg = head ? rg  : lg;
            const float* bv = head ? rb  : lb;
            const float* pb = head ? rpb : lpb;
            float v1 = 0.f, v2 = 0.f;
            if (tid < HH) {
                float w = pw[tid];
                float wg = w * gg[tid];
                g_wg[head][tid] = wg;
                v1 = wg;
                v2 = w * bv[tid];
            }
            float c1 = blockSum256(v1, red8);
            float c2 = blockSum256(v2, red8);
            if (tid == 0) { g_c[head][0] = c1; g_c[head][1] = c2 + pb[0]; }
            __syncthreads();
        }
    }

    const float* W; const float* B;
    if      (m == 0) { W = w0; B = b0; }
    else if (m == 1) { W = w1; B = b1; }
    else if (m == 2) { W = w2; B = b2; }
    else if (m == 3) { W = w3; B = b3; }
    else             { W = w4; B = b4; }

    int t0 = blockIdx.x * T1;
    for (int idx = tid; idx < T1 * HH; idx += 256) {
        int t = idx >> 7, c = idx & 127;
        sh[c * 12 + t] = hid[(t0 + t) * HH + c];
    }
    __syncthreads();

    // Each thread reduces K rows [kh*64, kh*64+64) with 8-deep prefetch.
    const float* Wh = W + (kh * 64) * HH + j;
    ull acc[4];
    if (kh == 0) {
        float bj = B[j];
        ull bj2 = pk(bj, bj);
#pragma unroll
        for (int q = 0; q < 4; q++) acc[q] = bj2;
    } else {
#pragma unroll
        for (int q = 0; q < 4; q++) acc[q] = 0ull;
    }

    float wcur[8];
#pragma unroll
    for (int u = 0; u < 8; u++) wcur[u] = Wh[u * HH];
#pragma unroll
    for (int kb = 0; kb < 64; kb += 8) {
        float wnxt[8];
        if (kb + 8 < 64) {
#pragma unroll
            for (int u = 0; u < 8; u++) wnxt[u] = Wh[(kb + 8 + u) * HH];
        }
#pragma unroll
        for (int u = 0; u < 8; u++) {
            ull wv = pk(wcur[u], wcur[u]);
            const float4* hp4 = (const float4*)&sh[(kh * 64 + kb + u) * 12];
            float4 f0 = hp4[0], f1 = hp4[1];
            acc[0] = fma2(pk(f0.x, f0.y), wv, acc[0]);
            acc[1] = fma2(pk(f0.z, f0.w), wv, acc[1]);
            acc[2] = fma2(pk(f1.x, f1.y), wv, acc[2]);
            acc[3] = fma2(pk(f1.z, f1.w), wv, acc[3]);
        }
        if (kb + 8 < 64) {
#pragma unroll
            for (int u = 0; u < 8; u++) wcur[u] = wnxt[u];
        }
    }

    // Combine the two K halves.
    if (kh) {
        ull* cc = &comb[j * 5];
#pragma unroll
        for (int q = 0; q < 4; q++) cc[q] = acc[q];
    }
    __syncthreads();
    if (!kh) {
        const ull* cc = &comb[j * 5];
#pragma unroll
        for (int q = 0; q < 4; q++) acc[q] = add2(acc[q], cc[q]);
    }

    if (m < 4) {
        if (!kh) {
            float* O = g_proj[m];
#pragma unroll
            for (int q = 0; q < 4; q++) {
                float lo, hi; upk(acc[q], lo, hi);
                O[(t0 + 2 * q) * HH + j] = lo;
                O[(t0 + 2 * q + 1) * HH + j] = hi;
            }
        }
    } else {
        // action tail: gelu -> LN -> 7 logits, in-smem (sh reused, stride 129).
        __syncthreads();
        if (!kh) {
#pragma unroll
            for (int q = 0; q < 4; q++) {
                float lo, hi; upk(acc[q], lo, hi);
                sh[(2 * q) * 129 + j]     = gelu_t(lo);
                sh[(2 * q + 1) * 129 + j] = gelu_t(hi);
            }
        }
        __syncthreads();
        if (tid < 128) {
            int w = tid >> 5, l = tid & 31;
#pragma unroll
            for (int tt = 0; tt < 2; tt++) {
                int t = w * 2 + tt;
                float v[4];
                float s = 0.f, s2 = 0.f;
#pragma unroll
                for (int k = 0; k < 4; k++) {
                    v[k] = sh[t * 129 + l + 32 * k];
                    s += v[k];
                    s2 = fmaf(v[k], v[k], s2);
                }
                s = warpSum(s);
                s2 = warpSum(s2);
                float mean = s * (1.0f / HH);
                float var = s2 * (1.0f / HH) - mean * mean;
                float rstd = rsqrtf(var + EPSF);
                float ln[4];
#pragma unroll
                for (int k = 0; k < 4; k++) {
                    int jj = l + 32 * k;
                    ln[k] = fmaf((v[k] - mean) * rstd, alg[jj], alb[jj]);
                }
#pragma unroll
                for (int a = 0; a < AA; a++) {
                    float d = 0.f;
#pragma unroll
                    for (int k = 0; k < 4; k++) {
                        int jj = l + 32 * k;
                        d = fmaf(ln[k], aw2[jj * AA + a], d);
                    }
                    d = warpSum(d);
                    if (l == 0) g_logits[(t0 + t) * AA + a] = d + ab2[a];
                }
            }
        }
    }
}

// k2: pointer pair scores. Persistent, 6 blocks/SM, dynamic tile counter.
// Tile = 16i x 32j, warp handles 2 i (IR=2). (R13 best-measured config.)
__global__ __launch_bounds__(256, 6) void k2_scores(float* __restrict__ out) {
    __shared__ float hd_s[16 * HH];     // [i][h]
    __shared__ float2 hv_s[65 * 33];    // [hh][j], padding row for prefetch
    __shared__ float wg_s[2][HH + 2];   // padded
    __shared__ unsigned int s_tile;

    int tid = threadIdx.x;
    if (tid < HH) { wg_s[0][tid] = g_wg[0][tid]; wg_s[1][tid] = g_wg[1][tid]; }
    if (tid < 2)  { wg_s[tid][HH] = 0.f; wg_s[tid][HH + 1] = 0.f; }

    const ull cA = pk(0.7978845608f * 0.044715f, 0.7978845608f * 0.044715f);
    const ull cB = pk(0.7978845608f, 0.7978845608f);

    int jl = tid & 31;
    int ib = (tid >> 5) * 2;   // warp's 2 i-rows

    while (true) {
        if (tid == 0) s_tile = atomicAdd(&g_tile_ctr, 1u);
        __syncthreads();               // orders s_tile AND protects smem reuse
        unsigned int tile = s_tile;
        if (tile >= NTILES) break;

        int bh = tile >> 9;                       // 4 (b,head) groups
        int b = bh >> 1, head = bh & 1;
        int rest = tile & 511;
        int i0 = (rest >> 4) * 16, j0 = (rest & 15) * 32;

        const float* hv = g_proj[head * 2 + 0] + b * SS * HH;
        const float* hd = g_proj[head * 2 + 1] + b * SS * HH;

        {
            const float4* src = (const float4*)(hd + i0 * HH);
            float4* dst = (float4*)hd_s;
            for (int k = tid; k < 16 * HH / 4; k += 256) dst[k] = src[k];
        }
        {
            int j = tid >> 3;
            int cg = tid & 7;
            const float4* src = (const float4*)(hv + (j0 + j) * HH + cg * 16);
#pragma unroll
            for (int q = 0; q < 4; q++) {
                float4 v = src[q];
                int hh = cg * 8 + q * 2;
                hv_s[hh * 33 + j] = make_float2(v.x, v.y);
                hv_s[(hh + 1) * 33 + j] = make_float2(v.z, v.w);
            }
        }
        __syncthreads();

        const ull* hdb = (const ull*)&hd_s[ib * HH];   // rows ib, ib+1
        const ull* wgp = (const ull*)wg_s[head];
        const ull* hvp = (const ull*)hv_s + jl;

        // accumulate y = 2*gelu(x):  y = x + x*tanh(u)
        ull s0[2], s1[2], sd[2];
#pragma unroll
        for (int i = 0; i < 2; i++) { s0[i] = 0ull; s1[i] = 0ull; sd[i] = 0ull; }

        ull hvv = hvp[0];
        ull wgv = wgp[0];
#pragma unroll 4
        for (int hh = 0; hh < HH / 2; hh++) {
            ull hvv_n = hvp[(hh + 1) * 33];   // row 64 = padding row, safe
            ull wgv_n = wgp[hh + 1];          // element 64 = padding, safe
#pragma unroll
            for (int i = 0; i < 2; i++) {
                ull x  = add2(hdb[i * 64 + hh], hvv);
                ull x2 = mul2(x, x);
                ull u  = mul2(x, fma2(cA, x2, cB));
                ull t  = tanh2(u);
                ull y  = fma2(x, t, x);
                s0[i] = add2(s0[i], y);
                s1[i] = fma2(y, y, s1[i]);
                sd[i] = fma2(wgv, y, sd[i]);
            }
            hvv = hvv_n;
            wgv = wgv_n;
        }

        float c1 = g_c[head][0], c2 = g_c[head][1];
        float* op = out + BB * SS * AA + head * (BB * SS * SS) + b * (SS * SS)
                  + (i0 + ib) * SS + (j0 + jl);
#pragma unroll
        for (int i = 0; i < 2; i++) {
            float a0, a1, q0, q1, d0, d1;
            upk(s0[i], a0, a1); upk(s1[i], q0, q1); upk(sd[i], d0, d1);
            float fs0 = a0 + a1, fs1 = q0 + q1, fsd = d0 + d1;
            float m    = fs0 * (1.0f / (2.0f * HH));
            float eg2  = fs1 * (1.0f / (4.0f * HH));
            float var  = eg2 - m * m;
            float rstd = rsqrtf(var + EPSF);
            float score = fmaf(rstd, fmaf(-m, c1, 0.5f * fsd), c2);
            op[i * SS] = score;
        }
    }
}

// kD: log-softmaxes, warp-per-row, 512-thread blocks (16 warps).
// blocks [0,128): 16 pointer rows each. blocks 128,129: action lsm (b = blk-128).
__global__ __launch_bounds__(512) void kD_lsm(float* __restrict__ out) {
    int w = threadIdx.x >> 5, l = threadIdx.x & 31;
    int blk = blockIdx.x;
    if (blk < 2 * BB * SS / 16) {
        int row = blk * 16 + w;
        float4* p = (float4*)(out + BB * SS * AA + row * SS);
        float4 v[4];
        float mx = -INFINITY;
#pragma unroll
        for (int k = 0; k < 4; k++) {
            v[k] = p[l + 32 * k];
            mx = fmaxf(mx, fmaxf(fmaxf(v[k].x, v[k].y), fmaxf(v[k].z, v[k].w)));
        }
        mx = warpMax(mx);
        float s = 0.f;
#pragma unroll
        for (int k = 0; k < 4; k++)
            s += __expf(v[k].x - mx) + __expf(v[k].y - mx) + __expf(v[k].z - mx) + __expf(v[k].w - mx);
        s = warpSum(s);
        float lgs = mx + __logf(s);
#pragma unroll
        for (int k = 0; k < 4; k++) {
            v[k].x -= lgs; v[k].y -= lgs; v[k].z -= lgs; v[k].w -= lgs;
            p[l + 32 * k] = v[k];
        }
    } else {
        int b = blk - 2 * BB * SS / 16;
        if (w < AA) {
            int a = w;
            const float* lg2 = g_logits + b * SS * AA + a;
            float v[16];
            float mx = -INFINITY;
#pragma unroll
            for (int k = 0; k < 16; k++) {
                v[k] = lg2[(l + 32 * k) * AA];
                mx = fmaxf(mx, v[k]);
            }
            mx = warpMax(mx);
            float s = 0.f;
#pragma unroll
            for (int k = 0; k < 16; k++) s += __expf(v[k] - mx);
            s = warpSum(s);
            float lgs = mx + __logf(s);
            float* o = out + b * SS * AA + a;
#pragma unroll
            for (int k = 0; k < 16; k++) o[(l + 32 * k) * AA] = v[k] - lgs;
        }
    }
}

extern "C" void kernel_launch(void* const* d_in, const int* in_sizes, int n_in,
                              void* d_out, int out_size) {
    const float* hiddens = (const float*)d_in[0];
    const float* aw1     = (const float*)d_in[1];
    const float* ab1     = (const float*)d_in[2];
    const float* a_ln_g  = (const float*)d_in[3];
    const float* a_ln_b  = (const float*)d_in[4];
    const float* aw2     = (const float*)d_in[5];
    const float* ab2     = (const float*)d_in[6];
    const float* lhid_w  = (const float*)d_in[7];
    const float* lhid_b  = (const float*)d_in[8];
    const float* lhead_w = (const float*)d_in[9];
    const float* lhead_b = (const float*)d_in[10];
    const float* l_ln_g  = (const float*)d_in[11];
    const float* l_ln_b  = (const float*)d_in[12];
    const float* l_proj_w = (const float*)d_in[13];
    const float* l_proj_b = (const float*)d_in[14];
    const float* rhid_w  = (const float*)d_in[15];
    const float* rhid_b  = (const float*)d_in[16];
    const float* rhead_w = (const float*)d_in[17];
    const float* rhead_b = (const float*)d_in[18];
    const float* r_ln_g  = (const float*)d_in[19];
    const float* r_ln_b  = (const float*)d_in[20];
    const float* r_proj_w = (const float*)d_in[21];
    const float* r_proj_b = (const float*)d_in[22];
    float* out = (float*)d_out;

    kA_proj<<<dim3(BB * SS / T1, 5), 256>>>(hiddens,
        lhid_w, lhid_b, lhead_w, lhead_b, rhid_w, rhid_b, rhead_w, rhead_b, aw1, ab1,
        l_proj_w, l_ln_g, l_ln_b, l_proj_b, r_proj_w, r_ln_g, r_ln_b, r_proj_b,
        a_ln_g, a_ln_b, aw2, ab2);
    k2_scores<<<K2_GRID, 256>>>(out);
    kD_lsm<<<2 * BB * SS / 16 + BB, 512>>>(out);
}